// round 4
// baseline (speedup 1.0000x reference)
#include <cuda_runtime.h>
#include <cuda_fp16.h>
#include <cstdint>

#define BATCH 4
#define TLEN  4096
#define HDIM  1024
#define MROWS (BATCH * TLEN)   // 16384
#define WIN   8
#define WSZ   9

// Scratch (device globals; cudaMalloc forbidden)
__device__ __half g_qh[MROWS * HDIM];        // fp16 q (scores only)
__device__ __half g_kh[MROWS * HDIM];        // fp16 k (scores only)
__device__ float  g_v [MROWS * HDIM];        // fp32 v
__device__ __half g_xh[MROWS * HDIM];        // fp16 states
__device__ __half g_wh[3 * HDIM * HDIM];     // fp16 Wq|Wk|Wv

// ---------------- PTX helpers ----------------
__device__ __forceinline__ uint32_t smem_u32(const void* p) {
    uint32_t a;
    asm("{ .reg .u64 t; cvta.to.shared.u64 t, %1; cvt.u32.u64 %0, t; }" : "=r"(a) : "l"(p));
    return a;
}
__device__ __forceinline__ void cp_async16(uint32_t sdst, const void* g) {
    asm volatile("cp.async.cg.shared.global [%0], [%1], 16;" :: "r"(sdst), "l"(g));
}
__device__ __forceinline__ void cp_commit() {
    asm volatile("cp.async.commit_group;" ::: "memory");
}
template<int N>
__device__ __forceinline__ void cp_wait() {
    asm volatile("cp.async.wait_group %0;" :: "n"(N) : "memory");
}
__device__ __forceinline__ void ldmatrix_x4(uint32_t r[4], uint32_t addr) {
    asm volatile("ldmatrix.sync.aligned.m8n8.x4.shared.b16 {%0,%1,%2,%3}, [%4];"
                 : "=r"(r[0]), "=r"(r[1]), "=r"(r[2]), "=r"(r[3]) : "r"(addr));
}
__device__ __forceinline__ void mma_f16(float c[4], const uint32_t a[4], const uint32_t b[2]) {
    asm volatile(
        "mma.sync.aligned.m16n8k16.row.col.f32.f16.f16.f32 "
        "{%0,%1,%2,%3}, {%4,%5,%6,%7}, {%8,%9}, {%0,%1,%2,%3};"
        : "+f"(c[0]), "+f"(c[1]), "+f"(c[2]), "+f"(c[3])
        : "r"(a[0]), "r"(a[1]), "r"(a[2]), "r"(a[3]), "r"(b[0]), "r"(b[1]));
}

// ---------------- prepass: fp32 -> fp16 ----------------
__global__ __launch_bounds__(256) void conv_states_kernel(const float* __restrict__ x) {
    int i = blockIdx.x * 256 + threadIdx.x;         // float4 index, 4,194,304 total
    float4 v = ((const float4*)x)[i];
    ((__half2*)g_xh)[2 * i]     = __floats2half2_rn(v.x, v.y);
    ((__half2*)g_xh)[2 * i + 1] = __floats2half2_rn(v.z, v.w);
}
__global__ __launch_bounds__(256) void conv_w_kernel(const float* __restrict__ Wq,
                                                     const float* __restrict__ Wk,
                                                     const float* __restrict__ Wv) {
    int i = blockIdx.x * 256 + threadIdx.x;         // float4 index, 786,432 total
    const float* s; __half* d; int j;
    if (i < 262144)      { s = Wq; d = g_wh;           j = i; }
    else if (i < 524288) { s = Wk; d = g_wh + 1048576; j = i - 262144; }
    else                 { s = Wv; d = g_wh + 2097152; j = i - 524288; }
    float4 v = ((const float4*)s)[j];
    ((__half2*)d)[2 * j]     = __floats2half2_rn(v.x, v.y);
    ((__half2*)d)[2 * j + 1] = __floats2half2_rn(v.z, v.w);
}

// ---------------- fp16 QKV GEMM ----------------
// BM=128, BN=128, BK=32 halfs (64B rows). 3-stage cp.async pipeline.
// Smem swizzle: 16B chunk c of row r stored at chunk (c ^ ((r>>1)&3)).
#define BK 32
#define ROW_BYTES 64                  // BK * 2
#define TILE_BYTES (128 * ROW_BYTES)  // 8 KB
#define STAGE_BYTES (2 * TILE_BYTES)  // A + B = 16 KB
#define NSTAGE 3
#define NK (HDIM / BK)                // 32

__device__ __forceinline__ uint32_t sw_off(int r, int c) {   // bytes within one tile
    return (uint32_t)(r * ROW_BYTES + ((c ^ ((r >> 1) & 3)) << 4));
}

__global__ __launch_bounds__(256, 2)
void qkv_gemm_kernel(const float* __restrict__ bq,
                     const float* __restrict__ bk,
                     const float* __restrict__ bv)
{
    __shared__ __align__(128) char smem[NSTAGE * STAGE_BYTES];   // 48 KB
    const uint32_t sb = smem_u32(smem);

    const int tid  = threadIdx.x;
    const int warp = tid >> 5;
    const int lane = tid & 31;
    const int m0 = blockIdx.x * 128;
    const int n0 = blockIdx.y * 128;
    const int z  = blockIdx.z;

    const __half* Xh = g_xh;
    const __half* Wh = g_wh + (size_t)z * HDIM * HDIM;
    const float* bias = (z == 0) ? bq : (z == 1) ? bk : bv;

    const int wm = (warp & 3) * 32;    // warp row in block tile
    const int wn = (warp >> 2) * 64;   // warp col

    float c[2][8][4];
    #pragma unroll
    for (int mt = 0; mt < 2; ++mt)
        #pragma unroll
        for (int nt = 0; nt < 8; ++nt)
            #pragma unroll
            for (int i = 0; i < 4; ++i) c[mt][nt][i] = 0.f;

    const int r0g = tid >> 2;          // row for granule pass 0 (0..63)
    const int cg  = tid & 3;           // 16B chunk

    auto load_tile = [&](int kt, int buf) {
        const uint32_t sa = sb + buf * STAGE_BYTES;
        const uint32_t sbm = sa + TILE_BYTES;
        const int k0 = kt * BK;
        #pragma unroll
        for (int i = 0; i < 2; ++i) {
            int r = r0g + i * 64;
            cp_async16(sa + sw_off(r, cg),
                       Xh + (size_t)(m0 + r) * HDIM + k0 + cg * 8);
            cp_async16(sbm + sw_off(r, cg),
                       Wh + (size_t)(n0 + r) * HDIM + k0 + cg * 8);
        }
        cp_commit();
    };

    load_tile(0, 0);
    load_tile(1, 1);
    load_tile(2, 2);

    for (int kt = 0; kt < NK; ++kt) {
        const int buf = kt % NSTAGE;
        cp_wait<2>();
        __syncthreads();

        const uint32_t sa  = sb + buf * STAGE_BYTES;
        const uint32_t sbm = sa + TILE_BYTES;

        #pragma unroll
        for (int kk = 0; kk < BK; kk += 16) {
            uint32_t a[2][4];
            #pragma unroll
            for (int mt = 0; mt < 2; ++mt) {
                int row = wm + mt * 16 + (lane & 15);
                int ch  = (kk >> 3) + (lane >> 4);
                ldmatrix_x4(a[mt], sa + sw_off(row, ch));
            }
            uint32_t b[4][4];
            #pragma unroll
            for (int np = 0; np < 4; ++np) {
                int row = wn + np * 16 + (lane & 7) + ((lane >> 4) << 3);
                int ch  = (kk >> 3) + ((lane >> 3) & 1);
                ldmatrix_x4(b[np], sbm + sw_off(row, ch));
            }
            #pragma unroll
            for (int mt = 0; mt < 2; ++mt)
                #pragma unroll
                for (int nt = 0; nt < 8; ++nt)
                    mma_f16(c[mt][nt], a[mt], &b[nt >> 1][(nt & 1) * 2]);
        }
        __syncthreads();
        if (kt + NSTAGE < NK) load_tile(kt + NSTAGE, buf);
    }

    // Epilogue: add bias; q,k -> fp16, v -> fp32
    const int g  = lane >> 2;
    const int tg = lane & 3;
    #pragma unroll
    for (int mt = 0; mt < 2; ++mt) {
        #pragma unroll
        for (int nt = 0; nt < 8; ++nt) {
            int row = m0 + wm + mt * 16 + g;
            int col = n0 + wn + nt * 8 + 2 * tg;
            float b0 = bias[col], b1 = bias[col + 1];
            float v00 = c[mt][nt][0] + b0, v01 = c[mt][nt][1] + b1;
            float v10 = c[mt][nt][2] + b0, v11 = c[mt][nt][3] + b1;
            if (z < 2) {
                __half* oh = (z == 0) ? g_qh : g_kh;
                *(__half2*)(oh + (size_t)row * HDIM + col)       = __floats2half2_rn(v00, v01);
                *(__half2*)(oh + (size_t)(row + 8) * HDIM + col) = __floats2half2_rn(v10, v11);
            } else {
                *(float2*)(g_v + (size_t)row * HDIM + col)       = make_float2(v00, v01);
                *(float2*)(g_v + (size_t)(row + 8) * HDIM + col) = make_float2(v10, v11);
            }
        }
    }
}

// ---------------- sliding-window attention: warp per row ----------------
__device__ __forceinline__ void dot8(float& acc, uint4 a, uint4 b) {
    const __half2* ah = (const __half2*)&a;
    const __half2* bh = (const __half2*)&b;
    #pragma unroll
    for (int j = 0; j < 4; ++j) {
        float2 af = __half22float2(ah[j]);
        float2 bf = __half22float2(bh[j]);
        acc += af.x * bf.x + af.y * bf.y;
    }
}

__global__ __launch_bounds__(128) void attn_kernel(float* __restrict__ out)
{
    const int warp = threadIdx.x >> 5;
    const int lane = threadIdx.x & 31;
    const int row  = blockIdx.x * 4 + warp;
    const int t    = row & (TLEN - 1);
    const int wstart = (t < WIN) ? (WIN - t) : 0;

    const uint4* q4 = (const uint4*)(g_qh + (size_t)row * HDIM);

    float acc[WSZ];
    #pragma unroll
    for (int w = 0; w < WSZ; ++w) acc[w] = 0.f;

    // scores: 1024 dims = 128 uint4 (8 halfs each); 4 chunks per lane
    #pragma unroll
    for (int i = 0; i < 4; ++i) {
        const int idx = lane + i * 32;
        const uint4 qv = q4[idx];
        #pragma unroll
        for (int w = 0; w < WSZ; ++w) {
            if (w >= wstart) {
                const uint4 kv = ((const uint4*)(g_kh + (size_t)(row - WIN + w) * HDIM))[idx];
                dot8(acc[w], qv, kv);
            }
        }
    }

    float wgt[WSZ];
    float mx = -1e30f;
    #pragma unroll
    for (int w = 0; w < WSZ; ++w) {
        float v = acc[w];
        #pragma unroll
        for (int off = 16; off; off >>= 1)
            v += __shfl_xor_sync(0xFFFFFFFFu, v, off);
        float s = (w >= wstart) ? v * 0.03125f : -1e30f;   // 1/sqrt(1024)
        wgt[w] = s;
        mx = fmaxf(mx, s);
    }
    float den = 0.f;
    #pragma unroll
    for (int w = 0; w < WSZ; ++w) {
        float e = (w >= wstart) ? __expf(wgt[w] - mx) : 0.f;
        wgt[w] = e;
        den += e;
    }
    const float inv = 1.f / den;
    #pragma unroll
    for (int w = 0; w < WSZ; ++w) wgt[w] *= inv;

    // output: v fp32, 256 float4 per row; 8 chunks per lane
    float4* o4 = (float4*)(out + (size_t)row * HDIM);
    #pragma unroll
    for (int i = 0; i < 8; ++i) {
        const int idx = lane + i * 32;
        float4 o = make_float4(0.f, 0.f, 0.f, 0.f);
        #pragma unroll
        for (int w = 0; w < WSZ; ++w) {
            if (w >= wstart) {
                const float4 vv = ((const float4*)(g_v + (size_t)(row - WIN + w) * HDIM))[idx];
                o.x += wgt[w] * vv.x; o.y += wgt[w] * vv.y;
                o.z += wgt[w] * vv.z; o.w += wgt[w] * vv.w;
            }
        }
        o4[idx] = o;
    }
}

// ---------------- launch ----------------
extern "C" void kernel_launch(void* const* d_in, const int* in_sizes, int n_in,
                              void* d_out, int out_size)
{
    const float* states = (const float*)d_in[0];
    const float* Wq = (const float*)d_in[1];
    const float* bq = (const float*)d_in[2];
    const float* Wk = (const float*)d_in[3];
    const float* bk = (const float*)d_in[4];
    const float* Wv = (const float*)d_in[5];
    const float* bv = (const float*)d_in[6];
    float* out = (float*)d_out;

    conv_states_kernel<<<16384, 256>>>(states);
    conv_w_kernel<<<3072, 256>>>(Wq, Wk, Wv);

    dim3 grid(MROWS / 128, HDIM / 128, 3);   // 128 x 8 x 3
    qkv_gemm_kernel<<<grid, 256>>>(bq, bk, bv);

    attn_kernel<<<MROWS / 4, 128>>>(out);
}

// round 5
// speedup vs baseline: 1.1094x; 1.1094x over previous
#include <cuda_runtime.h>
#include <cuda_fp16.h>
#include <cstdint>

#define BATCH 4
#define TLEN  4096
#define HDIM  1024
#define MROWS (BATCH * TLEN)   // 16384
#define WIN   8
#define WSZ   9

// Scratch (device globals; cudaMalloc forbidden)
__device__ __half g_qh[MROWS * HDIM];
__device__ __half g_kh[MROWS * HDIM];
__device__ __half g_vh[MROWS * HDIM];
__device__ __half g_xh[MROWS * HDIM];        // fp16 states
__device__ __half g_wh[3 * HDIM * HDIM];     // fp16 Wq|Wk|Wv

// ---------------- PTX helpers ----------------
__device__ __forceinline__ uint32_t smem_u32(const void* p) {
    uint32_t a;
    asm("{ .reg .u64 t; cvta.to.shared.u64 t, %1; cvt.u32.u64 %0, t; }" : "=r"(a) : "l"(p));
    return a;
}
__device__ __forceinline__ void cp_async16(uint32_t sdst, const void* g) {
    asm volatile("cp.async.cg.shared.global [%0], [%1], 16;" :: "r"(sdst), "l"(g));
}
__device__ __forceinline__ void cp_commit() {
    asm volatile("cp.async.commit_group;" ::: "memory");
}
template<int N>
__device__ __forceinline__ void cp_wait() {
    asm volatile("cp.async.wait_group %0;" :: "n"(N) : "memory");
}
__device__ __forceinline__ void ldmatrix_x4(uint32_t r[4], uint32_t addr) {
    asm volatile("ldmatrix.sync.aligned.m8n8.x4.shared.b16 {%0,%1,%2,%3}, [%4];"
                 : "=r"(r[0]), "=r"(r[1]), "=r"(r[2]), "=r"(r[3]) : "r"(addr));
}
__device__ __forceinline__ void mma_f16(float c[4], const uint32_t a[4], const uint32_t b[2]) {
    asm volatile(
        "mma.sync.aligned.m16n8k16.row.col.f32.f16.f16.f32 "
        "{%0,%1,%2,%3}, {%4,%5,%6,%7}, {%8,%9}, {%0,%1,%2,%3};"
        : "+f"(c[0]), "+f"(c[1]), "+f"(c[2]), "+f"(c[3])
        : "r"(a[0]), "r"(a[1]), "r"(a[2]), "r"(a[3]), "r"(b[0]), "r"(b[1]));
}

// ---------------- prepass: fp32 -> fp16 ----------------
__global__ __launch_bounds__(256) void conv_states_kernel(const float* __restrict__ x) {
    int i = blockIdx.x * 256 + threadIdx.x;         // float4 index, 4,194,304 total
    float4 v = ((const float4*)x)[i];
    ((__half2*)g_xh)[2 * i]     = __floats2half2_rn(v.x, v.y);
    ((__half2*)g_xh)[2 * i + 1] = __floats2half2_rn(v.z, v.w);
}
__global__ __launch_bounds__(256) void conv_w_kernel(const float* __restrict__ Wq,
                                                     const float* __restrict__ Wk,
                                                     const float* __restrict__ Wv) {
    int i = blockIdx.x * 256 + threadIdx.x;         // float4 index, 786,432 total
    const float* s; __half* d; int j;
    if (i < 262144)      { s = Wq; d = g_wh;           j = i; }
    else if (i < 524288) { s = Wk; d = g_wh + 1048576; j = i - 262144; }
    else                 { s = Wv; d = g_wh + 2097152; j = i - 524288; }
    float4 v = ((const float4*)s)[j];
    ((__half2*)d)[2 * j]     = __floats2half2_rn(v.x, v.y);
    ((__half2*)d)[2 * j + 1] = __floats2half2_rn(v.z, v.w);
}

// ---------------- fp16 QKV GEMM ----------------
// BM=128, BN=128, BK=32 halfs. 4-stage cp.async pipeline, ONE sync per k-iter.
#define BK 32
#define ROW_BYTES 64                  // BK * 2
#define TILE_BYTES (128 * ROW_BYTES)  // 8 KB
#define STAGE_BYTES (2 * TILE_BYTES)  // A + B = 16 KB
#define NSTAGE 4
#define NK (HDIM / BK)                // 32

__device__ __forceinline__ uint32_t sw_off(int r, int c) {   // bytes within one tile
    return (uint32_t)(r * ROW_BYTES + ((c ^ ((r >> 1) & 3)) << 4));
}

__global__ __launch_bounds__(256, 2)
void qkv_gemm_kernel(const float* __restrict__ bq,
                     const float* __restrict__ bk,
                     const float* __restrict__ bv)
{
    __shared__ __align__(128) char smem[NSTAGE * STAGE_BYTES];   // 64 KB
    const uint32_t sb = smem_u32(smem);

    const int tid  = threadIdx.x;
    const int warp = tid >> 5;
    const int lane = tid & 31;
    const int m0 = blockIdx.x * 128;
    const int n0 = blockIdx.y * 128;
    const int z  = blockIdx.z;

    const __half* Xh = g_xh;
    const __half* Wh = g_wh + (size_t)z * HDIM * HDIM;
    const float* bias = (z == 0) ? bq : (z == 1) ? bk : bv;
    __half* outp = (z == 0) ? g_qh : (z == 1) ? g_kh : g_vh;

    const int wm = (warp & 3) * 32;
    const int wn = (warp >> 2) * 64;

    float c[2][8][4];
    #pragma unroll
    for (int mt = 0; mt < 2; ++mt)
        #pragma unroll
        for (int nt = 0; nt < 8; ++nt)
            #pragma unroll
            for (int i = 0; i < 4; ++i) c[mt][nt][i] = 0.f;

    const int r0g = tid >> 2;
    const int cg  = tid & 3;

    auto load_tile = [&](int kt, int buf) {
        const uint32_t sa = sb + buf * STAGE_BYTES;
        const uint32_t sbm = sa + TILE_BYTES;
        const int k0 = kt * BK;
        #pragma unroll
        for (int i = 0; i < 2; ++i) {
            int r = r0g + i * 64;
            cp_async16(sa + sw_off(r, cg),
                       Xh + (size_t)(m0 + r) * HDIM + k0 + cg * 8);
            cp_async16(sbm + sw_off(r, cg),
                       Wh + (size_t)(n0 + r) * HDIM + k0 + cg * 8);
        }
        cp_commit();
    };

    load_tile(0, 0);
    load_tile(1, 1);
    load_tile(2, 2);

    for (int kt = 0; kt < NK; ++kt) {
        const int buf = kt & 3;
        cp_wait<2>();
        __syncthreads();
        // stage (kt+3)&3 == (kt-1)&3 was fully consumed before this sync
        if (kt + 3 < NK) load_tile(kt + 3, (kt + 3) & 3);
        else             cp_commit();          // keep group arithmetic exact

        const uint32_t sa  = sb + buf * STAGE_BYTES;
        const uint32_t sbm = sa + TILE_BYTES;

        #pragma unroll
        for (int kk = 0; kk < BK; kk += 16) {
            uint32_t a[2][4];
            #pragma unroll
            for (int mt = 0; mt < 2; ++mt) {
                int row = wm + mt * 16 + (lane & 15);
                int ch  = (kk >> 3) + (lane >> 4);
                ldmatrix_x4(a[mt], sa + sw_off(row, ch));
            }
            uint32_t b[4][4];
            #pragma unroll
            for (int np = 0; np < 4; ++np) {
                int row = wn + np * 16 + (lane & 7) + ((lane >> 4) << 3);
                int ch  = (kk >> 3) + ((lane >> 3) & 1);
                ldmatrix_x4(b[np], sbm + sw_off(row, ch));
            }
            #pragma unroll
            for (int mt = 0; mt < 2; ++mt)
                #pragma unroll
                for (int nt = 0; nt < 8; ++nt)
                    mma_f16(c[mt][nt], a[mt], &b[nt >> 1][(nt & 1) * 2]);
        }
    }

    // Epilogue: add bias, fp16 stores
    const int g  = lane >> 2;
    const int tg = lane & 3;
    #pragma unroll
    for (int mt = 0; mt < 2; ++mt) {
        #pragma unroll
        for (int nt = 0; nt < 8; ++nt) {
            int row = m0 + wm + mt * 16 + g;
            int col = n0 + wn + nt * 8 + 2 * tg;
            float b0 = bias[col], b1 = bias[col + 1];
            *(__half2*)(outp + (size_t)row * HDIM + col) =
                __floats2half2_rn(c[mt][nt][0] + b0, c[mt][nt][1] + b1);
            *(__half2*)(outp + (size_t)(row + 8) * HDIM + col) =
                __floats2half2_rn(c[mt][nt][2] + b0, c[mt][nt][3] + b1);
        }
    }
}

// ---------------- sliding-window attention: smem-tiled ----------------
#define A_ROWS 16
#define A_LOAD 24                      // A_ROWS + WIN halo
#define A_KBYTES (A_LOAD * 2048)       // 48 KB
#define A_SMEM (2 * A_KBYTES)          // 96 KB

__device__ __forceinline__ void dot8(float& acc, uint4 a, uint4 b) {
    const __half2* ah = (const __half2*)&a;
    const __half2* bh = (const __half2*)&b;
    #pragma unroll
    for (int j = 0; j < 4; ++j) {
        float2 af = __half22float2(ah[j]);
        float2 bf = __half22float2(bh[j]);
        acc += af.x * bf.x + af.y * bf.y;
    }
}
__device__ __forceinline__ void axpy8(float o[8], float w, uint4 v) {
    const __half2* vh = (const __half2*)&v;
    #pragma unroll
    for (int j = 0; j < 4; ++j) {
        float2 f = __half22float2(vh[j]);
        o[2 * j]     += w * f.x;
        o[2 * j + 1] += w * f.y;
    }
}

__global__ __launch_bounds__(256) void attn_kernel(float* __restrict__ out)
{
    extern __shared__ __align__(16) char asmem[];
    const __half* ks = (const __half*)asmem;
    const __half* vs = (const __half*)(asmem + A_KBYTES);
    const uint32_t sb = smem_u32(asmem);

    const int tid = threadIdx.x;
    const int r0  = blockIdx.x * A_ROWS;

    // stage k,v rows [r0-8, r0+16) -> smem (clamped; invalid taps are masked)
    #pragma unroll
    for (int p = 0; p < 12; ++p) {
        int gidx = tid + p * 256;              // 0..3071
        int s = gidx >> 7, cidx = gidx & 127;
        int gr = r0 - WIN + s; if (gr < 0) gr = 0;
        cp_async16(sb + s * 2048 + cidx * 16,
                   g_kh + (size_t)gr * HDIM + cidx * 8);
        cp_async16(sb + A_KBYTES + s * 2048 + cidx * 16,
                   g_vh + (size_t)gr * HDIM + cidx * 8);
    }
    cp_commit();
    cp_wait<0>();
    __syncthreads();

    const int warp = tid >> 5;
    const int lane = tid & 31;

    #pragma unroll
    for (int j = 0; j < 2; ++j) {
        const int lr  = warp * 2 + j;          // 0..15
        const int row = r0 + lr;
        const int t   = row & (TLEN - 1);
        const int wstart = (t < WIN) ? (WIN - t) : 0;

        const uint4* q4 = (const uint4*)(g_qh + (size_t)row * HDIM);

        float acc[WSZ];
        #pragma unroll
        for (int w = 0; w < WSZ; ++w) acc[w] = 0.f;

        if (wstart == 0) {
            #pragma unroll
            for (int i = 0; i < 4; ++i) {
                const int idx = lane + i * 32;
                const uint4 qv = q4[idx];
                #pragma unroll
                for (int w = 0; w < WSZ; ++w) {
                    const uint4 kv = *(const uint4*)(ks + (size_t)(lr + w) * HDIM + idx * 8);
                    dot8(acc[w], qv, kv);
                }
            }
        } else {
            #pragma unroll
            for (int i = 0; i < 4; ++i) {
                const int idx = lane + i * 32;
                const uint4 qv = q4[idx];
                #pragma unroll
                for (int w = 0; w < WSZ; ++w) {
                    if (w >= wstart) {
                        const uint4 kv = *(const uint4*)(ks + (size_t)(lr + w) * HDIM + idx * 8);
                        dot8(acc[w], qv, kv);
                    }
                }
            }
        }

        float wgt[WSZ];
        float mx = -1e30f;
        #pragma unroll
        for (int w = 0; w < WSZ; ++w) {
            float v = acc[w];
            #pragma unroll
            for (int off = 16; off; off >>= 1)
                v += __shfl_xor_sync(0xFFFFFFFFu, v, off);
            float s = (w >= wstart) ? v * 0.03125f : -1e30f;   // 1/sqrt(1024)
            wgt[w] = s;
            mx = fmaxf(mx, s);
        }
        float den = 0.f;
        #pragma unroll
        for (int w = 0; w < WSZ; ++w) {
            float e = (w >= wstart) ? __expf(wgt[w] - mx) : 0.f;
            wgt[w] = e;
            den += e;
        }
        const float inv = 1.f / den;
        #pragma unroll
        for (int w = 0; w < WSZ; ++w) wgt[w] *= inv;

        #pragma unroll
        for (int i = 0; i < 4; ++i) {
            const int idx = lane + i * 32;
            float o[8];
            #pragma unroll
            for (int x = 0; x < 8; ++x) o[x] = 0.f;
            if (wstart == 0) {
                #pragma unroll
                for (int w = 0; w < WSZ; ++w) {
                    const uint4 vv = *(const uint4*)(vs + (size_t)(lr + w) * HDIM + idx * 8);
                    axpy8(o, wgt[w], vv);
                }
            } else {
                #pragma unroll
                for (int w = 0; w < WSZ; ++w) {
                    if (w >= wstart) {
                        const uint4 vv = *(const uint4*)(vs + (size_t)(lr + w) * HDIM + idx * 8);
                        axpy8(o, wgt[w], vv);
                    }
                }
            }
            float4* op = (float4*)(out + (size_t)row * HDIM + idx * 8);
            op[0] = make_float4(o[0], o[1], o[2], o[3]);
            op[1] = make_float4(o[4], o[5], o[6], o[7]);
        }
    }
}

// ---------------- launch ----------------
extern "C" void kernel_launch(void* const* d_in, const int* in_sizes, int n_in,
                              void* d_out, int out_size)
{
    const float* states = (const float*)d_in[0];
    const float* Wq = (const float*)d_in[1];
    const float* bq = (const float*)d_in[2];
    const float* Wk = (const float*)d_in[3];
    const float* bk = (const float*)d_in[4];
    const float* Wv = (const float*)d_in[5];
    const float* bv = (const float*)d_in[6];
    float* out = (float*)d_out;

    cudaFuncSetAttribute(attn_kernel,
                         cudaFuncAttributeMaxDynamicSharedMemorySize, A_SMEM);

    conv_states_kernel<<<16384, 256>>>(states);
    conv_w_kernel<<<3072, 256>>>(Wq, Wk, Wv);

    dim3 grid(MROWS / 128, HDIM / 128, 3);   // 128 x 8 x 3
    qkv_gemm_kernel<<<grid, 256>>>(bq, bk, bv);

    attn_kernel<<<MROWS / A_ROWS, 256, A_SMEM>>>(out);
}

// round 6
// speedup vs baseline: 1.1590x; 1.0448x over previous
#include <cuda_runtime.h>
#include <cuda_fp16.h>
#include <cstdint>

#define BATCH 4
#define TLEN  4096
#define HDIM  1024
#define MROWS (BATCH * TLEN)   // 16384
#define WIN   8
#define WSZ   9

// Scratch (device globals; cudaMalloc forbidden)
__device__ __half g_qh[MROWS * HDIM];
__device__ __half g_kh[MROWS * HDIM];
__device__ __half g_vh[MROWS * HDIM];
__device__ __half g_xh[MROWS * HDIM];        // fp16 states
__device__ __half g_wh[3 * HDIM * HDIM];     // fp16 Wq|Wk|Wv

// ---------------- PTX helpers ----------------
__device__ __forceinline__ uint32_t smem_u32(const void* p) {
    uint32_t a;
    asm("{ .reg .u64 t; cvta.to.shared.u64 t, %1; cvt.u32.u64 %0, t; }" : "=r"(a) : "l"(p));
    return a;
}
__device__ __forceinline__ void cp_async16(uint32_t sdst, const void* g) {
    asm volatile("cp.async.cg.shared.global [%0], [%1], 16;" :: "r"(sdst), "l"(g));
}
__device__ __forceinline__ void cp_commit() {
    asm volatile("cp.async.commit_group;" ::: "memory");
}
template<int N>
__device__ __forceinline__ void cp_wait() {
    asm volatile("cp.async.wait_group %0;" :: "n"(N) : "memory");
}
__device__ __forceinline__ void ldmatrix_x4(uint32_t r[4], uint32_t addr) {
    asm volatile("ldmatrix.sync.aligned.m8n8.x4.shared.b16 {%0,%1,%2,%3}, [%4];"
                 : "=r"(r[0]), "=r"(r[1]), "=r"(r[2]), "=r"(r[3]) : "r"(addr));
}
__device__ __forceinline__ void mma_f16(float c[4], const uint32_t a[4], const uint32_t b[2]) {
    asm volatile(
        "mma.sync.aligned.m16n8k16.row.col.f32.f16.f16.f32 "
        "{%0,%1,%2,%3}, {%4,%5,%6,%7}, {%8,%9}, {%0,%1,%2,%3};"
        : "+f"(c[0]), "+f"(c[1]), "+f"(c[2]), "+f"(c[3])
        : "r"(a[0]), "r"(a[1]), "r"(a[2]), "r"(a[3]), "r"(b[0]), "r"(b[1]));
}

// ---------------- fused prepass: fp32 -> fp16 ----------------
// 4,194,304 states float4 + 786,432 weight float4 = 4,980,736 total
__global__ __launch_bounds__(256) void conv_kernel(const float* __restrict__ x,
                                                   const float* __restrict__ Wq,
                                                   const float* __restrict__ Wk,
                                                   const float* __restrict__ Wv) {
    int i = blockIdx.x * 256 + threadIdx.x;
    const float* s; __half* d; int j;
    if (i < 4194304)      { s = x;  d = g_xh;           j = i; }
    else {
        int m = i - 4194304;
        if (m < 262144)      { s = Wq; d = g_wh;           j = m; }
        else if (m < 524288) { s = Wk; d = g_wh + 1048576; j = m - 262144; }
        else                 { s = Wv; d = g_wh + 2097152; j = m - 524288; }
    }
    float4 v = ((const float4*)s)[j];
    ((__half2*)d)[2 * j]     = __floats2half2_rn(v.x, v.y);
    ((__half2*)d)[2 * j + 1] = __floats2half2_rn(v.z, v.w);
}

// ---------------- fp16 QKV GEMM ----------------
// BM=128, BN=128, BK=32 halfs. 4-stage cp.async pipeline, ONE sync per k-iter.
#define BK 32
#define ROW_BYTES 64                  // BK * 2
#define TILE_BYTES (128 * ROW_BYTES)  // 8 KB
#define STAGE_BYTES (2 * TILE_BYTES)  // A + B = 16 KB
#define NSTAGE 4
#define NK (HDIM / BK)                // 32

__device__ __forceinline__ uint32_t sw_off(int r, int c) {   // bytes within one tile
    return (uint32_t)(r * ROW_BYTES + ((c ^ ((r >> 1) & 3)) << 4));
}

__global__ __launch_bounds__(256, 2)
void qkv_gemm_kernel(const float* __restrict__ bq,
                     const float* __restrict__ bk,
                     const float* __restrict__ bv)
{
    __shared__ __align__(128) char smem[NSTAGE * STAGE_BYTES];   // 64 KB
    const uint32_t sb = smem_u32(smem);

    const int tid  = threadIdx.x;
    const int warp = tid >> 5;
    const int lane = tid & 31;
    const int m0 = blockIdx.x * 128;
    const int n0 = blockIdx.y * 128;
    const int z  = blockIdx.z;

    const __half* Xh = g_xh;
    const __half* Wh = g_wh + (size_t)z * HDIM * HDIM;
    const float* bias = (z == 0) ? bq : (z == 1) ? bk : bv;
    __half* outp = (z == 0) ? g_qh : (z == 1) ? g_kh : g_vh;

    const int wm = (warp & 3) * 32;
    const int wn = (warp >> 2) * 64;

    float c[2][8][4];
    #pragma unroll
    for (int mt = 0; mt < 2; ++mt)
        #pragma unroll
        for (int nt = 0; nt < 8; ++nt)
            #pragma unroll
            for (int i = 0; i < 4; ++i) c[mt][nt][i] = 0.f;

    const int r0g = tid >> 2;
    const int cg  = tid & 3;

    auto load_tile = [&](int kt, int buf) {
        const uint32_t sa = sb + buf * STAGE_BYTES;
        const uint32_t sbm = sa + TILE_BYTES;
        const int k0 = kt * BK;
        #pragma unroll
        for (int i = 0; i < 2; ++i) {
            int r = r0g + i * 64;
            cp_async16(sa + sw_off(r, cg),
                       Xh + (size_t)(m0 + r) * HDIM + k0 + cg * 8);
            cp_async16(sbm + sw_off(r, cg),
                       Wh + (size_t)(n0 + r) * HDIM + k0 + cg * 8);
        }
        cp_commit();
    };

    load_tile(0, 0);
    load_tile(1, 1);
    load_tile(2, 2);

    for (int kt = 0; kt < NK; ++kt) {
        const int buf = kt & 3;
        cp_wait<2>();
        __syncthreads();
        if (kt + 3 < NK) load_tile(kt + 3, (kt + 3) & 3);
        else             cp_commit();          // keep group arithmetic exact

        const uint32_t sa  = sb + buf * STAGE_BYTES;
        const uint32_t sbm = sa + TILE_BYTES;

        #pragma unroll
        for (int kk = 0; kk < BK; kk += 16) {
            uint32_t a[2][4];
            #pragma unroll
            for (int mt = 0; mt < 2; ++mt) {
                int row = wm + mt * 16 + (lane & 15);
                int ch  = (kk >> 3) + (lane >> 4);
                ldmatrix_x4(a[mt], sa + sw_off(row, ch));
            }
            uint32_t b[4][4];
            #pragma unroll
            for (int np = 0; np < 4; ++np) {
                int row = wn + np * 16 + (lane & 7) + ((lane >> 4) << 3);
                int ch  = (kk >> 3) + ((lane >> 3) & 1);
                ldmatrix_x4(b[np], sbm + sw_off(row, ch));
            }
            #pragma unroll
            for (int mt = 0; mt < 2; ++mt)
                #pragma unroll
                for (int nt = 0; nt < 8; ++nt)
                    mma_f16(c[mt][nt], a[mt], &b[nt >> 1][(nt & 1) * 2]);
        }
    }

    // Epilogue: add bias, fp16 stores
    const int g  = lane >> 2;
    const int tg = lane & 3;
    #pragma unroll
    for (int mt = 0; mt < 2; ++mt) {
        #pragma unroll
        for (int nt = 0; nt < 8; ++nt) {
            int row = m0 + wm + mt * 16 + g;
            int col = n0 + wn + nt * 8 + 2 * tg;
            float b0 = bias[col], b1 = bias[col + 1];
            *(__half2*)(outp + (size_t)row * HDIM + col) =
                __floats2half2_rn(c[mt][nt][0] + b0, c[mt][nt][1] + b1);
            *(__half2*)(outp + (size_t)(row + 8) * HDIM + col) =
                __floats2half2_rn(c[mt][nt][2] + b0, c[mt][nt][3] + b1);
        }
    }
}

// ---------------- sliding-window attention: smem-tiled, 1 row/warp ----------------
#define A_ROWS 16
#define A_LOAD 24                      // A_ROWS + WIN halo
#define A_KBYTES (A_LOAD * 2048)       // 48 KB
#define A_SMEM (2 * A_KBYTES)          // 96 KB
#define A_THREADS 512

__device__ __forceinline__ void dot8(float& acc, uint4 a, uint4 b) {
    const __half2* ah = (const __half2*)&a;
    const __half2* bh = (const __half2*)&b;
    #pragma unroll
    for (int j = 0; j < 4; ++j) {
        float2 af = __half22float2(ah[j]);
        float2 bf = __half22float2(bh[j]);
        acc += af.x * bf.x + af.y * bf.y;
    }
}
__device__ __forceinline__ void axpy8(float o[8], float w, uint4 v) {
    const __half2* vh = (const __half2*)&v;
    #pragma unroll
    for (int j = 0; j < 4; ++j) {
        float2 f = __half22float2(vh[j]);
        o[2 * j]     += w * f.x;
        o[2 * j + 1] += w * f.y;
    }
}

__global__ __launch_bounds__(A_THREADS, 2) void attn_kernel(float* __restrict__ out)
{
    extern __shared__ __align__(16) char asmem[];
    const __half* ks = (const __half*)asmem;
    const __half* vs = (const __half*)(asmem + A_KBYTES);
    const uint32_t sb = smem_u32(asmem);

    const int tid = threadIdx.x;
    const int r0  = blockIdx.x * A_ROWS;

    // stage k,v rows [r0-8, r0+16) -> smem (clamped; invalid taps are masked)
    #pragma unroll
    for (int p = 0; p < 6; ++p) {
        int gidx = tid + p * A_THREADS;        // 0..3071
        int s = gidx >> 7, cidx = gidx & 127;
        int gr = r0 - WIN + s; if (gr < 0) gr = 0;
        cp_async16(sb + s * 2048 + cidx * 16,
                   g_kh + (size_t)gr * HDIM + cidx * 8);
        cp_async16(sb + A_KBYTES + s * 2048 + cidx * 16,
                   g_vh + (size_t)gr * HDIM + cidx * 8);
    }
    cp_commit();
    cp_wait<0>();
    __syncthreads();

    const int warp = tid >> 5;
    const int lane = tid & 31;

    const int lr  = warp;                  // 0..15
    const int row = r0 + lr;
    const int t   = row & (TLEN - 1);
    const int wstart = (t < WIN) ? (WIN - t) : 0;

    const uint4* q4 = (const uint4*)(g_qh + (size_t)row * HDIM);

    float acc[WSZ];
    #pragma unroll
    for (int w = 0; w < WSZ; ++w) acc[w] = 0.f;

    if (wstart == 0) {
        #pragma unroll
        for (int i = 0; i < 4; ++i) {
            const int idx = lane + i * 32;
            const uint4 qv = q4[idx];
            #pragma unroll
            for (int w = 0; w < WSZ; ++w) {
                const uint4 kv = *(const uint4*)(ks + (size_t)(lr + w) * HDIM + idx * 8);
                dot8(acc[w], qv, kv);
            }
        }
    } else {
        #pragma unroll
        for (int i = 0; i < 4; ++i) {
            const int idx = lane + i * 32;
            const uint4 qv = q4[idx];
            #pragma unroll
            for (int w = 0; w < WSZ; ++w) {
                if (w >= wstart) {
                    const uint4 kv = *(const uint4*)(ks + (size_t)(lr + w) * HDIM + idx * 8);
                    dot8(acc[w], qv, kv);
                }
            }
        }
    }

    float wgt[WSZ];
    float mx = -1e30f;
    #pragma unroll
    for (int w = 0; w < WSZ; ++w) {
        float v = acc[w];
        #pragma unroll
        for (int off = 16; off; off >>= 1)
            v += __shfl_xor_sync(0xFFFFFFFFu, v, off);
        float s = (w >= wstart) ? v * 0.03125f : -1e30f;   // 1/sqrt(1024)
        wgt[w] = s;
        mx = fmaxf(mx, s);
    }
    float den = 0.f;
    #pragma unroll
    for (int w = 0; w < WSZ; ++w) {
        float e = (w >= wstart) ? __expf(wgt[w] - mx) : 0.f;
        wgt[w] = e;
        den += e;
    }
    const float inv = 1.f / den;
    #pragma unroll
    for (int w = 0; w < WSZ; ++w) wgt[w] *= inv;

    #pragma unroll
    for (int i = 0; i < 4; ++i) {
        const int idx = lane + i * 32;
        float o[8];
        #pragma unroll
        for (int x = 0; x < 8; ++x) o[x] = 0.f;
        if (wstart == 0) {
            #pragma unroll
            for (int w = 0; w < WSZ; ++w) {
                const uint4 vv = *(const uint4*)(vs + (size_t)(lr + w) * HDIM + idx * 8);
                axpy8(o, wgt[w], vv);
            }
        } else {
            #pragma unroll
            for (int w = 0; w < WSZ; ++w) {
                if (w >= wstart) {
                    const uint4 vv = *(const uint4*)(vs + (size_t)(lr + w) * HDIM + idx * 8);
                    axpy8(o, wgt[w], vv);
                }
            }
        }
        float4* op = (float4*)(out + (size_t)row * HDIM + idx * 8);
        op[0] = make_float4(o[0], o[1], o[2], o[3]);
        op[1] = make_float4(o[4], o[5], o[6], o[7]);
    }
}

// ---------------- launch ----------------
extern "C" void kernel_launch(void* const* d_in, const int* in_sizes, int n_in,
                              void* d_out, int out_size)
{
    const float* states = (const float*)d_in[0];
    const float* Wq = (const float*)d_in[1];
    const float* bq = (const float*)d_in[2];
    const float* Wk = (const float*)d_in[3];
    const float* bk = (const float*)d_in[4];
    const float* Wv = (const float*)d_in[5];
    const float* bv = (const float*)d_in[6];
    float* out = (float*)d_out;

    cudaFuncSetAttribute(attn_kernel,
                         cudaFuncAttributeMaxDynamicSharedMemorySize, A_SMEM);

    conv_kernel<<<19456, 256>>>(states, Wq, Wk, Wv);

    dim3 grid(MROWS / 128, HDIM / 128, 3);   // 128 x 8 x 3
    qkv_gemm_kernel<<<grid, 256>>>(bq, bk, bv);

    attn_kernel<<<MROWS / A_ROWS, A_THREADS, A_SMEM>>>(out);
}